// round 6
// baseline (speedup 1.0000x reference)
#include <cuda_runtime.h>
#include <cstdint>

#define B_ 8
#define N_ 1024
#define I_ 64
#define O_ 32
#define H_ 4
#define NW 32
#define PS 40              // padded P-tile row stride: bank(8q4+g+8nc) conflict-free
#define LOG2E 1.4426950408889634f

// ---- device scratch ----
__device__ float    g_proj[B_*H_*N_*O_];    // [bh][j][o], tf32-rounded
__device__ float2   g_srcsp[B_*H_*N_];      // (src*L, gain*prior*L)
__device__ float    g_dstsc[B_*H_*N_];      // dst*L
__device__ unsigned g_adjbits[N_*NW];

__device__ __forceinline__ float tf32r(float x) {
    uint32_t r;
    asm("cvt.rna.tf32.f32 %0, %1;" : "=r"(r) : "f"(x));
    return __uint_as_float(r);
}
__device__ __forceinline__ float ex2f(float x) {
    float r;
    asm("ex2.approx.f32 %0, %1;" : "=f"(r) : "f"(x));
    return r;
}

// =============== K01: pack (blocks 0..127) + projection/scores (128..383) ===============
__global__ __launch_bounds__(256) void k01_prep(
    const int* __restrict__ adj,
    const float* __restrict__ x, const float* __restrict__ weight,
    const float* __restrict__ bias, const float* __restrict__ attn_src,
    const float* __restrict__ attn_dst, const float* __restrict__ beta,
    const float* __restrict__ prior)
{
    __shared__ float s_x[32*I_];           // 8KB
    __shared__ float s_ws[H_*I_];          // w_src scaled
    __shared__ float s_wd[H_*I_];          // w_dst scaled
    __shared__ float s_c[8];
    int tid = threadIdx.x, lane = tid & 31, w = tid >> 5;

    if (blockIdx.x < 128) {
        int i = blockIdx.x * 8 + w;
        const int4* a4 = (const int4*)(adj + (size_t)i * N_);
        int g = lane >> 3;
        unsigned gmask = 0xFFu << (g * 8);
        int sh = (lane & 7) * 4;
#pragma unroll
        for (int c4 = 0; c4 < 8; c4++) {
            int4 v = a4[c4 * 32 + lane];
            unsigned nib = (unsigned)(v.x != 0) | ((unsigned)(v.y != 0) << 1)
                         | ((unsigned)(v.z != 0) << 2) | ((unsigned)(v.w != 0) << 3);
            unsigned word = __reduce_or_sync(gmask, nib << sh);
            if ((lane & 7) == 0) g_adjbits[i * NW + c4 * 4 + g] = word;
        }
        return;
    }

    int pb = blockIdx.x - 128;
    int g0 = pb * 32;
    int b  = g0 >> 10;

    const float4* gx4 = (const float4*)(x + (size_t)g0 * I_);
    ((float4*)s_x)[tid]       = gx4[tid];
    ((float4*)s_x)[tid + 256] = gx4[tid + 256];

    {
        int h = tid >> 6;
        const float4* wrow = (const float4*)(weight + (size_t)tid * O_);
        const float4* as4  = (const float4*)(attn_src + h * O_);
        const float4* ad4  = (const float4*)(attn_dst + h * O_);
        float accs = 0.f, accd = 0.f;
#pragma unroll
        for (int o4 = 0; o4 < 8; o4++) {
            float4 wv = wrow[o4], av = as4[o4], dv = ad4[o4];
            accs += wv.x*av.x + wv.y*av.y + wv.z*av.z + wv.w*av.w;
            accd += wv.x*dv.x + wv.y*dv.y + wv.z*dv.z + wv.w*dv.w;
        }
        s_ws[tid] = accs * LOG2E;
        s_wd[tid] = accd * LOG2E;
    }
    if (tid < 8) {
        int hh = tid & 3;
        const float* bb = bias + hh * O_;
        const float* aa = (tid < 4 ? attn_src : attn_dst) + hh * O_;
        float c = 0.f;
#pragma unroll
        for (int o = 0; o < O_; o++) c += bb[o] * aa[o];
        s_c[tid] = c * LOG2E;
    }
    __syncthreads();

    {
        int half = tid >> 7, ho = tid & 127;
        int h = ho >> 5, o = ho & 31;
        float wr[I_];
        const float* wp = weight + h * I_ * O_ + o;
#pragma unroll
        for (int i = 0; i < I_; i++) wr[i] = wp[i * O_];
        float bias_v = bias[ho];
        int bh = b * H_ + h;
        for (int q = 0; q < 16; q++) {
            int nl = half * 16 + q;
            int n = (g0 + nl) & 1023;
            float acc = bias_v;
            const float4* xs4 = (const float4*)(s_x + nl * I_);
#pragma unroll
            for (int i4 = 0; i4 < I_/4; i4++) {
                float4 xv = xs4[i4];
                acc = fmaf(xv.x, wr[4*i4+0], acc);
                acc = fmaf(xv.y, wr[4*i4+1], acc);
                acc = fmaf(xv.z, wr[4*i4+2], acc);
                acc = fmaf(xv.w, wr[4*i4+3], acc);
            }
            g_proj[((size_t)bh * N_ + n) * O_ + o] = tf32r(acc);
        }
    }

    {
        int role = tid >> 7;
        int n = (tid & 127) >> 2, hs = tid & 3;
        const float4* xv4 = (const float4*)(s_x + n * I_);
        const float4* wv4 = (const float4*)((role ? s_wd : s_ws) + hs * I_);
        float sc = s_c[role * 4 + hs];
#pragma unroll
        for (int i4 = 0; i4 < I_/4; i4++) {
            float4 xv = xv4[i4], wv = wv4[i4];
            sc += xv.x*wv.x + xv.y*wv.y + xv.z*wv.z + xv.w*wv.w;
        }
        int gidx = g0 + n;
        int idx = (b * H_ + hs) * N_ + (gidx & 1023);
        if (role) {
            g_dstsc[idx] = sc;
        } else {
            float bt = beta[hs];
            float gain = ((bt > 20.f) ? bt : log1pf(__expf(bt))) * LOG2E;
            g_srcsp[idx] = make_float2(sc, gain * prior[gidx]);
        }
    }
}

// =============== K2: 4-way j-split, register-fragment exp -> mma.sync tf32 ===============
// grid (16, H, B), 512 threads. Block: 64 dst rows. 4 groups of 4 warps, 256 j each.
__global__ __launch_bounds__(512, 2) void k2_attn(float* __restrict__ out) {
    __shared__ float2 s_ss[N_];            // 8KB  (reused as dn partials at merge)
    __shared__ float  s_P[4][64*PS];       // 40KB per-group P tiles (reused for acc merge)

    int tid = threadIdx.x, lane = tid & 31, w = tid >> 5;
    int h = blockIdx.y, b = blockIdx.z, bh = b * H_ + h;
    int row0 = blockIdx.x * 64;

    const float2* gss = g_srcsp + (size_t)bh * N_;
#pragma unroll
    for (int u = 0; u < 2; u++) s_ss[tid + u * 512] = gss[tid + u * 512];
    __syncthreads();

    int grp = w >> 2;                      // j-quarter 0..3
    int wl4 = w & 3;                       // warp within group
    int g   = lane >> 2;                   // 0..7 row group
    int q4  = lane & 3;                    // k slot
    int r_lo = wl4 * 16 + g, r_hi = r_lo + 8;
    float dst_lo = g_dstsc[(size_t)bh * N_ + row0 + r_lo];
    float dst_hi = g_dstsc[(size_t)bh * N_ + row0 + r_hi];
    const unsigned* adj_lo = g_adjbits + (size_t)(row0 + r_lo) * NW;
    const unsigned* adj_hi = g_adjbits + (size_t)(row0 + r_hi) * NW;

    float acc[4][4];
#pragma unroll
    for (int nc = 0; nc < 4; nc++)
#pragma unroll
        for (int k = 0; k < 4; k++) acc[nc][k] = 0.f;
    float dn_lo = 0.f, dn_hi = 0.f;

    const float4* gp4 = (const float4*)(g_proj + (size_t)bh * N_ * O_);
    float* Pbuf = s_P[grp];
    int lt = tid & 127;                    // group-local tid
    int barid = grp + 1;

    for (int tt = 0; tt < 4; tt++) {       // 4 tiles of 64 j per group
        int j0 = grp * 256 + tt * 64;
        if (tt) asm volatile("bar.sync %0, %1;" :: "r"(barid), "r"(128) : "memory");
        // stage 64-j P tile (512 float4 by 128 threads)
#pragma unroll
        for (int u = 0; u < 4; u++) {
            int idx = lt + u * 128;
            int j = idx >> 3, o4 = idx & 7;
            *(float4*)(Pbuf + j * PS + o4 * 4) = gp4[(j0 >> 2) * O_ + idx];
        }
        asm volatile("bar.sync %0, %1;" :: "r"(barid), "r"(128) : "memory");

#pragma unroll
        for (int w4 = 0; w4 < 2; w4++) {   // 2 adjacency words per 64-j tile
            int widx = (j0 >> 5) + w4;
            unsigned wlw = adj_lo[widx] >> q4;
            unsigned whw = adj_hi[widx] >> q4;
#pragma unroll
            for (int sub = 0; sub < 4; sub++) {
                int jb = (w4 * 4 + sub) * 8;       // local j base in tile
                float2 ss0 = s_ss[j0 + jb + q4];
                float2 ss1 = s_ss[j0 + jb + q4 + 4];

                float v0l = dst_lo + ss0.x, v0h = dst_hi + ss0.x;
                float v1l = dst_lo + ss1.x, v1h = dst_hi + ss1.x;
                float a0 = fmaf(0.4f, fabsf(v0l), fmaf(0.6f, v0l, ss0.y));
                float a1 = fmaf(0.4f, fabsf(v0h), fmaf(0.6f, v0h, ss0.y));
                float a2 = fmaf(0.4f, fabsf(v1l), fmaf(0.6f, v1l, ss1.y));
                float a3 = fmaf(0.4f, fabsf(v1h), fmaf(0.6f, v1h, ss1.y));

                float e0 = ((wlw >> (sub * 8)) & 1u)     ? ex2f(a0) : 0.f;
                float e1 = ((whw >> (sub * 8)) & 1u)     ? ex2f(a1) : 0.f;
                float e2 = ((wlw >> (sub * 8 + 4)) & 1u) ? ex2f(a2) : 0.f;
                float e3 = ((whw >> (sub * 8 + 4)) & 1u) ? ex2f(a3) : 0.f;
                e0 = tf32r(e0); e1 = tf32r(e1); e2 = tf32r(e2); e3 = tf32r(e3);
                dn_lo += e0 + e2;
                dn_hi += e1 + e3;

                uint32_t u0 = __float_as_uint(e0), u1 = __float_as_uint(e1);
                uint32_t u2 = __float_as_uint(e2), u3 = __float_as_uint(e3);
                const float* Pj0 = Pbuf + (jb + q4) * PS + g;
                const float* Pj1 = Pj0 + 4 * PS;
#pragma unroll
                for (int nc = 0; nc < 4; nc++) {
                    uint32_t b0 = __float_as_uint(Pj0[nc * 8]);
                    uint32_t b1 = __float_as_uint(Pj1[nc * 8]);
                    asm volatile(
                        "mma.sync.aligned.m16n8k8.row.col.f32.tf32.tf32.f32 "
                        "{%0,%1,%2,%3}, {%4,%5,%6,%7}, {%8,%9}, {%0,%1,%2,%3};"
                        : "+f"(acc[nc][0]), "+f"(acc[nc][1]), "+f"(acc[nc][2]), "+f"(acc[nc][3])
                        : "r"(u0), "r"(u1), "r"(u2), "r"(u3), "r"(b0), "r"(b1));
                }
            }
        }
    }

    // ---- merge 4 j-quarters (groups 1-3 -> smem, group 0 reduces) ----
    __syncthreads();
    float* red  = &s_P[0][0];              // 3 groups x 128 lanes x stride 17
    float* dnp  = (float*)s_ss;            // 3 groups x 256
    if (grp > 0) {
        int lb = wl4 * 32 + lane;
        float* ra = red + ((grp - 1) * 128 + lb) * 17;
#pragma unroll
        for (int nc = 0; nc < 4; nc++)
#pragma unroll
            for (int k = 0; k < 4; k++) ra[nc * 4 + k] = acc[nc][k];
        dnp[(grp - 1) * 256 + lb * 2]     = dn_lo;
        dnp[(grp - 1) * 256 + lb * 2 + 1] = dn_hi;
    }
    __syncthreads();
    if (grp == 0) {
        int lb = wl4 * 32 + lane;
#pragma unroll
        for (int pg = 0; pg < 3; pg++) {
            const float* ra = red + (pg * 128 + lb) * 17;
#pragma unroll
            for (int nc = 0; nc < 4; nc++)
#pragma unroll
                for (int k = 0; k < 4; k++) acc[nc][k] += ra[nc * 4 + k];
            dn_lo += dnp[pg * 256 + lb * 2];
            dn_hi += dnp[pg * 256 + lb * 2 + 1];
        }
#pragma unroll
        for (int off = 1; off <= 2; off <<= 1) {
            dn_lo += __shfl_xor_sync(0xffffffffu, dn_lo, off);
            dn_hi += __shfl_xor_sync(0xffffffffu, dn_hi, off);
        }
        float inv_lo = dn_lo > 0.f ? 1.f / dn_lo : 0.f;
        float inv_hi = dn_hi > 0.f ? 1.f / dn_hi : 0.f;

        float* orow_lo = out + ((size_t)b * N_ + row0 + r_lo) * (H_ * O_) + h * O_;
        float* orow_hi = out + ((size_t)b * N_ + row0 + r_hi) * (H_ * O_) + h * O_;
#pragma unroll
        for (int nc = 0; nc < 4; nc++) {
            float2 vlo = make_float2(acc[nc][0] * inv_lo, acc[nc][1] * inv_lo);
            float2 vhi = make_float2(acc[nc][2] * inv_hi, acc[nc][3] * inv_hi);
            *(float2*)(orow_lo + nc * 8 + 2 * q4) = vlo;
            *(float2*)(orow_hi + nc * 8 + 2 * q4) = vhi;
        }
    }
}

// =============== launch ===============
extern "C" void kernel_launch(void* const* d_in, const int* in_sizes, int n_in,
                              void* d_out, int out_size) {
    const float* x        = (const float*)d_in[0];
    const int*   adj      = (const int*)  d_in[1];
    const float* prior    = (const float*)d_in[2];
    const float* beta     = (const float*)d_in[3];
    const float* weight   = (const float*)d_in[4];
    const float* attn_src = (const float*)d_in[5];
    const float* attn_dst = (const float*)d_in[6];
    const float* bias     = (const float*)d_in[7];
    float* out = (float*)d_out;

    k01_prep<<<384, 256>>>(adj, x, weight, bias, attn_src, attn_dst, beta, prior);
    k2_attn<<<dim3(N_/64, H_, B_), 512>>>(out);
}